// round 14
// baseline (speedup 1.0000x reference)
#include <cuda_runtime.h>
#include <cstdint>

#define N_NODES 12288
#define H_DIM   128
#define E_EDGES 393216
#define NEGVAL  (-1000000000.0f)
#define ROW4    (N_NODES / 4)          // 3072 float4 per row
#define CAP     256                    // bucket capacity (Poisson(32), max~65)

#define D_GRID    592                  // 148 SMs x 4 blocks, one wave
#define D_THREADS 512
#define F4_PER_T  (ROW4 / D_THREADS)   // 6 float4 per thread

// Static scratch. g_cursor zero-init; self-restored by D each launch.
__device__ float g_d1[N_NODES];
__device__ float g_d2[N_NODES];
__device__ int   g_cursor[N_NODES];
__device__ int2  g_bucket[(size_t)N_NODES * CAP];  // (src_col, float_bits(value))

// ---------------------------------------------------------------------------
// A1: per-node dots. 1 warp/node, 1 float4 load per lane (proven 5.9us).
// ---------------------------------------------------------------------------
__global__ void dots_kernel(const float* __restrict__ h,
                            const float* __restrict__ W) {
    int t    = (int)(blockIdx.x * blockDim.x + threadIdx.x);
    int gw   = t >> 5;
    int lane = t & 31;
    if (gw >= N_NODES) return;

    const float4* hr4 = (const float4*)(h + (size_t)gw * H_DIM);
    const float4* w14 = (const float4*)(W);
    const float4* w24 = (const float4*)(W + H_DIM);
    float4 hv = __ldg(&hr4[lane]);
    float4 w1 = __ldg(&w14[lane]);
    float4 w2 = __ldg(&w24[lane]);
    float s1 = fmaf(hv.x, w1.x, fmaf(hv.y, w1.y, fmaf(hv.z, w1.z, hv.w * w1.w)));
    float s2 = fmaf(hv.x, w2.x, fmaf(hv.y, w2.y, fmaf(hv.z, w2.z, hv.w * w2.w)));
#pragma unroll
    for (int off = 16; off; off >>= 1) {
        s1 += __shfl_down_sync(0xffffffffu, s1, off);
        s2 += __shfl_down_sync(0xffffffffu, s2, off);
    }
    if (lane == 0) { g_d1[gw] = s1; g_d2[gw] = s2; }
}

// ---------------------------------------------------------------------------
// A2: place edges with precomputed values, ILP x4 (R9-proven). PDL: edge
//     loads + cursor atomics run pre-sync (independent of A1).
// ---------------------------------------------------------------------------
__global__ void place_kernel(const int*   __restrict__ src,
                             const int*   __restrict__ dst,
                             const float* __restrict__ wts,
                             const float* __restrict__ W,
                             const float* __restrict__ b) {
    int t  = (int)(blockIdx.x * blockDim.x + threadIdx.x);
    int e0 = t * 4;
    if (e0 >= E_EDGES) return;          // E multiple of 4

    int4   s4 = *(const int4*)  (src + e0);
    int4   d4 = *(const int4*)  (dst + e0);
    float4 w4 = *(const float4*)(wts + e0);
    float wlin = __ldg(&W[2 * H_DIM]);
    float bias = __ldg(&b[0]);

    int p0 = atomicAdd(&g_cursor[d4.x], 1);
    int p1 = atomicAdd(&g_cursor[d4.y], 1);
    int p2 = atomicAdd(&g_cursor[d4.z], 1);
    int p3 = atomicAdd(&g_cursor[d4.w], 1);

    cudaGridDependencySynchronize();    // wait for A1's d1/d2

    float a0 = g_d1[d4.x], a1 = g_d1[d4.y], a2 = g_d1[d4.z], a3 = g_d1[d4.w];
    float c0 = g_d2[s4.x], c1 = g_d2[s4.y], c2 = g_d2[s4.z], c3 = g_d2[s4.w];

    float v0 = a0 + c0 + fmaf(w4.x, wlin, bias);
    float v1 = a1 + c1 + fmaf(w4.y, wlin, bias);
    float v2 = a2 + c2 + fmaf(w4.z, wlin, bias);
    float v3 = a3 + c3 + fmaf(w4.w, wlin, bias);

    if (p0 < CAP) g_bucket[(size_t)d4.x * CAP + p0] = make_int2(s4.x, __float_as_int(v0));
    if (p1 < CAP) g_bucket[(size_t)d4.y * CAP + p1] = make_int2(s4.y, __float_as_int(v1));
    if (p2 < CAP) g_bucket[(size_t)d4.z * CAP + p2] = make_int2(s4.z, __float_as_int(v2));
    if (p3 < CAP) g_bucket[(size_t)d4.w * CAP + p3] = make_int2(s4.w, __float_as_int(v3));
}

// ---------------------------------------------------------------------------
// D: register-direct fill+merge. No 48KB row buffer: each thread emits its
//    6 float4s straight from registers (NEG4 patched from the tiny smem
//    bucket). Smem traffic/row drops 96KB -> ~1KB; the big fill loop and
//    read-back disappear. Store pattern (coalesced __stcs) unchanged.
// ---------------------------------------------------------------------------
__global__ __launch_bounds__(D_THREADS, 4)
void fill_merge_kernel(float4* __restrict__ out) {
    __shared__ int   s_col[CAP];
    __shared__ float s_val[CAP];
    const int tid = threadIdx.x;
    const float4 v = make_float4(NEGVAL, NEGVAL, NEGVAL, NEGVAL);

    cudaGridDependencySynchronize();             // buckets + cursors ready

    for (int r = blockIdx.x; r < N_NODES; r += D_GRID) {
        // broadcast cursor read; bucket entries -> smem (coalesced 8B loads)
        int c   = g_cursor[r];
        int cnt = (c < CAP) ? c : CAP;
        if (tid < cnt) {
            int2 ev = g_bucket[(size_t)r * CAP + tid];
            s_col[tid] = ev.x;
            s_val[tid] = __int_as_float(ev.y);
        }
        __syncthreads();                         // bucket visible; cursor reads done

        if (tid == 0) g_cursor[r] = 0;           // self-restore for next launch

        float4* dstp = out + (size_t)r * ROW4;
#pragma unroll
        for (int k = 0; k < F4_PER_T; k++) {
            const int i = tid + k * D_THREADS;   // float4 index (coalesced)
            float4 val = v;
            const int base = i * 4;
            for (int j = 0; j < cnt; j++) {      // broadcast LDS, predicated
                int cc = s_col[j];
                if ((cc >> 2) == i) {
                    float vv = s_val[j];
                    int m = cc - base;
                    if (m == 0) val.x = vv;
                    else if (m == 1) val.y = vv;
                    else if (m == 2) val.z = vv;
                    else val.w = vv;
                }
            }
            __stcs(&dstp[i], val);
        }
        __syncthreads();                         // scans done before smem reuse
    }
}

// ---------------------------------------------------------------------------
// Launch. Input order (metadata): h, sources, dests, weights, W, b
// ---------------------------------------------------------------------------
extern "C" void kernel_launch(void* const* d_in, const int* in_sizes, int n_in,
                              void* d_out, int out_size) {
    const float* h       = (const float*)d_in[0];
    const int*   sources = (const int*)  d_in[1];
    const int*   dests   = (const int*)  d_in[2];
    const float* weights = (const float*)d_in[3];
    const float* W       = (const float*)d_in[4];
    const float* b       = (const float*)d_in[5];
    float*       out     = (float*)d_out;

    // A1: dots (plain launch; serializes vs previous replay's D).
    dots_kernel<<<(N_NODES * 32) / 256, 256>>>(h, W);

    cudaLaunchAttribute pdl[1];
    pdl[0].id = cudaLaunchAttributeProgrammaticStreamSerialization;
    pdl[0].val.programmaticStreamSerializationAllowed = 1;

    // A2: place (PDL over A1).
    {
        cudaLaunchConfig_t cfg = {};
        cfg.gridDim  = dim3((E_EDGES / 4) / 256);
        cfg.blockDim = dim3(256);
        cfg.attrs    = pdl;
        cfg.numAttrs = 1;
        cudaLaunchKernelEx(&cfg, place_kernel, sources, dests, weights, W, b);
    }

    // D: register-direct fill+merge (PDL over A2). 4 blocks/SM, one wave.
    {
        cudaLaunchConfig_t cfg = {};
        cfg.gridDim  = dim3(D_GRID);
        cfg.blockDim = dim3(D_THREADS);
        cfg.attrs    = pdl;
        cfg.numAttrs = 1;
        cudaLaunchKernelEx(&cfg, fill_merge_kernel, (float4*)out);
    }
}

// round 15
// speedup vs baseline: 3.4914x; 3.4914x over previous
#include <cuda_runtime.h>
#include <cstdint>

#define N_NODES 12288
#define H_DIM   128
#define E_EDGES 393216
#define NEGVAL  (-1000000000.0f)
#define ROW4    (N_NODES / 4)          // 3072 float4 per row
#define CAP     256                    // bucket capacity (Poisson(32), max~65)

#define D_GRID    444                  // 148 SMs x 3 blocks -> one wave,
#define D_THREADS 512                  // leaves 512 thr slots/SM for A1 co-run

// Static scratch. g_cursor zero-init; self-restored by D each launch.
__device__ float g_d1[N_NODES];
__device__ float g_d2[N_NODES];
__device__ int   g_cursor[N_NODES];
__device__ int2  g_bucket[(size_t)N_NODES * CAP];  // (src_col, float_bits(value))

// ---------------------------------------------------------------------------
// A1: per-node dots. 1 warp/node, 1 float4 load per lane (proven).
//     IDEMPOTENT (same values every replay) and disjoint from everything D
//     touches -> safe to overlap the previous replay's D via PDL.
// ---------------------------------------------------------------------------
__global__ void dots_kernel(const float* __restrict__ h,
                            const float* __restrict__ W) {
    int t    = (int)(blockIdx.x * blockDim.x + threadIdx.x);
    int gw   = t >> 5;
    int lane = t & 31;
    if (gw >= N_NODES) return;

    const float4* hr4 = (const float4*)(h + (size_t)gw * H_DIM);
    const float4* w14 = (const float4*)(W);
    const float4* w24 = (const float4*)(W + H_DIM);
    float4 hv = __ldg(&hr4[lane]);
    float4 w1 = __ldg(&w14[lane]);
    float4 w2 = __ldg(&w24[lane]);
    float s1 = fmaf(hv.x, w1.x, fmaf(hv.y, w1.y, fmaf(hv.z, w1.z, hv.w * w1.w)));
    float s2 = fmaf(hv.x, w2.x, fmaf(hv.y, w2.y, fmaf(hv.z, w2.z, hv.w * w2.w)));
#pragma unroll
    for (int off = 16; off; off >>= 1) {
        s1 += __shfl_down_sync(0xffffffffu, s1, off);
        s2 += __shfl_down_sync(0xffffffffu, s2, off);
    }
    if (lane == 0) { g_d1[gw] = s1; g_d2[gw] = s2; }
}

// ---------------------------------------------------------------------------
// A2: place edges with precomputed values, ILP x4. Plain launch (NO PDL):
//     must hard-serialize after the previous replay's D (cursor atomics vs
//     D's cursor read/reset would corrupt the pipeline otherwise).
// ---------------------------------------------------------------------------
__global__ void place_kernel(const int*   __restrict__ src,
                             const int*   __restrict__ dst,
                             const float* __restrict__ wts,
                             const float* __restrict__ W,
                             const float* __restrict__ b) {
    int t  = (int)(blockIdx.x * blockDim.x + threadIdx.x);
    int e0 = t * 4;
    if (e0 >= E_EDGES) return;          // E multiple of 4

    int4   s4 = *(const int4*)  (src + e0);
    int4   d4 = *(const int4*)  (dst + e0);
    float4 w4 = *(const float4*)(wts + e0);
    float wlin = __ldg(&W[2 * H_DIM]);
    float bias = __ldg(&b[0]);

    float a0 = g_d1[d4.x], a1 = g_d1[d4.y], a2 = g_d1[d4.z], a3 = g_d1[d4.w];
    float c0 = g_d2[s4.x], c1 = g_d2[s4.y], c2 = g_d2[s4.z], c3 = g_d2[s4.w];

    int p0 = atomicAdd(&g_cursor[d4.x], 1);
    int p1 = atomicAdd(&g_cursor[d4.y], 1);
    int p2 = atomicAdd(&g_cursor[d4.z], 1);
    int p3 = atomicAdd(&g_cursor[d4.w], 1);

    float v0 = a0 + c0 + fmaf(w4.x, wlin, bias);
    float v1 = a1 + c1 + fmaf(w4.y, wlin, bias);
    float v2 = a2 + c2 + fmaf(w4.z, wlin, bias);
    float v3 = a3 + c3 + fmaf(w4.w, wlin, bias);

    if (p0 < CAP) g_bucket[(size_t)d4.x * CAP + p0] = make_int2(s4.x, __float_as_int(v0));
    if (p1 < CAP) g_bucket[(size_t)d4.y * CAP + p1] = make_int2(s4.y, __float_as_int(v1));
    if (p2 < CAP) g_bucket[(size_t)d4.z * CAP + p2] = make_int2(s4.z, __float_as_int(v2));
    if (p3 < CAP) g_bucket[(size_t)d4.w * CAP + p3] = make_int2(s4.w, __float_as_int(v3));
}

// ---------------------------------------------------------------------------
// D: fill + merge (R9-proven structure, 3 blocks/SM). PDL over A2: first
//    row's smem NEG prefill runs pre-sync. Cursor self-reset preserved.
// ---------------------------------------------------------------------------
__global__ __launch_bounds__(D_THREADS, 3)
void fill_merge_kernel(float4* __restrict__ out) {
    __shared__ float row[N_NODES];               // exactly 48 KB
    float4* row4 = (float4*)row;
    const float4 v = make_float4(NEGVAL, NEGVAL, NEGVAL, NEGVAL);
    const int tid = threadIdx.x;

    // Prefill first row's smem while A2 drains (touches no global state).
#pragma unroll
    for (int i = tid; i < ROW4; i += D_THREADS) row4[i] = v;

    cudaGridDependencySynchronize();             // buckets + cursors ready

    bool first = true;
    for (int r = blockIdx.x; r < N_NODES; r += D_GRID) {
        int c   = g_cursor[r];                   // broadcast; hidden under fill
        int cnt = (c < CAP) ? c : CAP;

        if (!first) {
#pragma unroll
            for (int i = tid; i < ROW4; i += D_THREADS) row4[i] = v;
        }
        first = false;
        __syncthreads();                         // all cursor[r] reads done

        if (tid == 0) g_cursor[r] = 0;           // self-restore for next launch

        const int2* bkt = &g_bucket[(size_t)r * CAP];
        for (int i = tid; i < cnt; i += D_THREADS) {
            int2 ev = bkt[i];
            row[ev.x] = __int_as_float(ev.y);    // dup races benign
        }
        __syncthreads();

        float4* dstp = out + (size_t)r * ROW4;
#pragma unroll
        for (int i = tid; i < ROW4; i += D_THREADS) __stcs(&dstp[i], row4[i]);
        __syncthreads();                         // stores done before smem reuse
    }
}

// ---------------------------------------------------------------------------
// Launch. Input order (metadata): h, sources, dests, weights, W, b
//   A1: PDL  -> overlaps previous replay's D (idempotent, disjoint state).
//   A2: plain -> hard barrier vs previous D (cursor safety).
//   D : PDL  -> overlaps A2's tail (proven R9 win).
// ---------------------------------------------------------------------------
extern "C" void kernel_launch(void* const* d_in, const int* in_sizes, int n_in,
                              void* d_out, int out_size) {
    const float* h       = (const float*)d_in[0];
    const int*   sources = (const int*)  d_in[1];
    const int*   dests   = (const int*)  d_in[2];
    const float* weights = (const float*)d_in[3];
    const float* W       = (const float*)d_in[4];
    const float* b       = (const float*)d_in[5];
    float*       out     = (float*)d_out;

    cudaLaunchAttribute pdl[1];
    pdl[0].id = cudaLaunchAttributeProgrammaticStreamSerialization;
    pdl[0].val.programmaticStreamSerializationAllowed = 1;

    // A1: dots (PDL -> may overlap previous replay's D).
    {
        cudaLaunchConfig_t cfg = {};
        cfg.gridDim  = dim3((N_NODES * 32) / 256);
        cfg.blockDim = dim3(256);
        cfg.attrs    = pdl;
        cfg.numAttrs = 1;
        cudaLaunchKernelEx(&cfg, dots_kernel, h, W);
    }

    // A2: place (plain launch -> waits for all prior work incl. previous D).
    place_kernel<<<(E_EDGES / 4) / 256, 256>>>(sources, dests, weights, W, b);

    // D: fill + merge (PDL over A2). 3 blocks/SM, one wave of 444.
    {
        cudaLaunchConfig_t cfg = {};
        cfg.gridDim  = dim3(D_GRID);
        cfg.blockDim = dim3(D_THREADS);
        cfg.attrs    = pdl;
        cfg.numAttrs = 1;
        cudaLaunchKernelEx(&cfg, fill_merge_kernel, (float4*)out);
    }
}